// round 11
// baseline (speedup 1.0000x reference)
#include <cuda_runtime.h>
#include <cuda_fp16.h>
#include <math.h>
#include <stdint.h>

// ---------------------------------------------------------------------------
// TransformerBlock on GB300 (sm_103a; PTX target compute_103 => portable
// features only: mma.sync / ldmatrix / cp.async).
// Round 10: instruction-mix fixes.
//   Attention was LDSM-bound (LDSM:MMA = 1.0 vs GEMM's proven 0.5): K and V
//   fragment loads switched to ldmatrix.x4 (2 fragment pairs per LDSM),
//   halving LDSM count. LN rewritten 2-warps-per-row (regs 64->~40,
//   occupancy-limited latency fixed). GEMM cores at MMA ceiling, unchanged.
// ---------------------------------------------------------------------------

#define MTOT   4096
#define CDIM   1024
#define HIDDIM 4096
#define NBATCH 2
#define SEQLEN 2048
#define NHEADS 16
#define HDIM   64
#define QKV_ST 3072

// ------------------------------ scratch ------------------------------------
__device__ float  g_x1[MTOT * CDIM];
__device__ __half g_h  [MTOT * CDIM];                        // LN out fp16
__device__ __half g_qkv[(size_t)MTOT * QKV_ST];              // packed Q|K|V
__device__ __half g_o  [MTOT * CDIM];                        // attn out fp16
__device__ __half g_f  [(size_t)MTOT * HIDDIM];              // FFN hidden fp16
__device__ __half g_wqkv[(size_t)3 * CDIM * CDIM];           // W^T packed qkv
__device__ __half g_wo [(size_t)CDIM * CDIM];
__device__ __half g_w1t[(size_t)HIDDIM * CDIM];
__device__ __half g_w2t[(size_t)CDIM * HIDDIM];

// --------------------------- helpers ---------------------------------------
__device__ __forceinline__ uint32_t smem_u32(const void* p) {
    uint32_t a;
    asm("{ .reg .u64 t; cvta.to.shared.u64 t, %1; cvt.u32.u64 %0, t; }"
        : "=r"(a) : "l"(p));
    return a;
}
__device__ __forceinline__ void cpasync16(uint32_t saddr, const void* g) {
    asm volatile("cp.async.cg.shared.global [%0], [%1], 16;"
                 :: "r"(saddr), "l"(g));
}
#define CP_COMMIT() asm volatile("cp.async.commit_group;" ::: "memory")
#define CP_WAIT(n)  asm volatile("cp.async.wait_group %0;" :: "n"(n) : "memory")

__device__ __forceinline__ void ldmA(uint32_t* a, uint32_t addr) {
    asm volatile("ldmatrix.sync.aligned.m8n8.x4.shared.b16 {%0,%1,%2,%3}, [%4];"
        : "=r"(a[0]), "=r"(a[1]), "=r"(a[2]), "=r"(a[3]) : "r"(addr));
}
__device__ __forceinline__ void ldmAT(uint32_t* a, uint32_t addr) {
    asm volatile("ldmatrix.sync.aligned.m8n8.x4.trans.shared.b16 {%0,%1,%2,%3}, [%4];"
        : "=r"(a[0]), "=r"(a[1]), "=r"(a[2]), "=r"(a[3]) : "r"(addr));
}
__device__ __forceinline__ void ldmB(uint32_t* b, uint32_t addr) {
    asm volatile("ldmatrix.sync.aligned.m8n8.x2.shared.b16 {%0,%1}, [%2];"
        : "=r"(b[0]), "=r"(b[1]) : "r"(addr));
}
__device__ __forceinline__ void mmaF16(float* d, const uint32_t* a,
                                       const uint32_t* b) {
    asm volatile(
        "mma.sync.aligned.m16n8k16.row.col.f32.f16.f16.f32 "
        "{%0,%1,%2,%3}, {%4,%5,%6,%7}, {%8,%9}, {%0,%1,%2,%3};"
        : "+f"(d[0]), "+f"(d[1]), "+f"(d[2]), "+f"(d[3])
        : "r"(a[0]), "r"(a[1]), "r"(a[2]), "r"(a[3]), "r"(b[0]), "r"(b[1]));
}
__device__ __forceinline__ uint32_t pack_f16(float lo, float hi) {
    uint32_t r;
    asm("cvt.rn.f16x2.f32 %0, %1, %2;" : "=r"(r) : "f"(hi), "f"(lo));
    return r;
}
__device__ __forceinline__ float gelu_exact(float x) {
    return 0.5f * x * (1.0f + erff(x * 0.70710678118654752f));
}
// FMA-pipe 2^x (no MUFU).
__device__ __forceinline__ float exp2_fast(float x) {
    x = fmaxf(x, -126.0f);
    const float z = x + 12582912.0f;
    const int   i = __float_as_int(z) - 0x4B400000;
    const float f = x - (z - 12582912.0f);
    float p =          1.3333558e-3f;
    p = fmaf(p, f, 9.6181291e-3f);
    p = fmaf(p, f, 5.5504109e-2f);
    p = fmaf(p, f, 2.4022651e-1f);
    p = fmaf(p, f, 6.9314718e-1f);
    p = fmaf(p, f, 1.0f);
    return __int_as_float(__float_as_int(p) + (i << 23));
}
#define C_SCALE 0.18033688f   // (1/sqrt(64)) * log2(e)

// ---------------------------------------------------------------------------
// LayerNorm -> fp16. 2 warps (64 thr) per row, 4 float4/thread, smem combine.
// Block 256 = 4 rows; grid MTOT/4.
// ---------------------------------------------------------------------------
__global__ __launch_bounds__(256) void ln_kernel(
    const float* __restrict__ in, const float* __restrict__ gamma,
    const float* __restrict__ beta, __half* __restrict__ oh)
{
    const int tid  = threadIdx.x;
    const int rloc = tid >> 6;            // 0..3 row within block
    const int sub  = tid & 63;            // 0..63 thread within row
    const int row  = blockIdx.x * 4 + rloc;
    const float4* rp = (const float4*)(in + (size_t)row * CDIM);

    float4 v[4];
    #pragma unroll
    for (int i = 0; i < 4; i++) v[i] = rp[sub + 64 * i];

    float s = 0.f, ss = 0.f;
    #pragma unroll
    for (int i = 0; i < 4; i++) {
        s  += v[i].x + v[i].y + v[i].z + v[i].w;
        ss += v[i].x * v[i].x + v[i].y * v[i].y +
              v[i].z * v[i].z + v[i].w * v[i].w;
    }
    #pragma unroll
    for (int o = 16; o > 0; o >>= 1) {
        s  += __shfl_xor_sync(0xffffffffu, s,  o);
        ss += __shfl_xor_sync(0xffffffffu, ss, o);
    }
    __shared__ float2 part[8];
    const int w = tid >> 5;
    if ((tid & 31) == 0) { part[w].x = s; part[w].y = ss; }
    __syncthreads();
    const float2 pa = part[rloc * 2 + 0];
    const float2 pb = part[rloc * 2 + 1];
    const float mu = (pa.x + pb.x) * (1.0f / CDIM);
    const float r  = rsqrtf((pa.y + pb.y) * (1.0f / CDIM) - mu * mu + 1e-5f);

    uint2* op = (uint2*)(oh + (size_t)row * CDIM);
    #pragma unroll
    for (int i = 0; i < 4; i++) {
        const float4 g4 = ((const float4*)gamma)[sub + 64 * i];
        const float4 b4 = ((const float4*)beta )[sub + 64 * i];
        uint2 o;
        o.x = pack_f16((v[i].x - mu) * r * g4.x + b4.x,
                       (v[i].y - mu) * r * g4.y + b4.y);
        o.y = pack_f16((v[i].z - mu) * r * g4.z + b4.z,
                       (v[i].w - mu) * r * g4.w + b4.w);
        op[sub + 64 * i] = o;
    }
}

// ---------------------------------------------------------------------------
// Weight transposes -> fp16 (side stream, off the critical path).
// ---------------------------------------------------------------------------
__global__ __launch_bounds__(256) void wtrans4_kernel(
    const float* __restrict__ Wq, const float* __restrict__ Wk,
    const float* __restrict__ Wv, const float* __restrict__ Wo,
    __half* __restrict__ wqkv, __half* __restrict__ wo)
{
    __shared__ float t[32][33];
    const int z  = blockIdx.z;
    const float* W = (z == 0) ? Wq : (z == 1) ? Wk : (z == 2) ? Wv : Wo;
    __half* T = (z < 3) ? (wqkv + (size_t)z * CDIM * CDIM) : wo;
    const int n0 = blockIdx.x * 32, k0 = blockIdx.y * 32;
    const int tx = threadIdx.x & 31, ty = threadIdx.x >> 5;
    #pragma unroll
    for (int i = ty; i < 32; i += 8)
        t[i][tx] = W[(size_t)(k0 + i) * CDIM + n0 + tx];
    __syncthreads();
    #pragma unroll
    for (int i = ty; i < 32; i += 8)
        T[(size_t)(n0 + i) * CDIM + k0 + tx] = __float2half_rn(t[tx][i]);
}

__global__ __launch_bounds__(256) void wtrans_kernel(
    const float* __restrict__ W, __half* __restrict__ T, int K, int N)
{
    __shared__ float t[32][33];
    const int n0 = blockIdx.x * 32, k0 = blockIdx.y * 32;
    const int tx = threadIdx.x & 31, ty = threadIdx.x >> 5;
    #pragma unroll
    for (int i = ty; i < 32; i += 8)
        t[i][tx] = W[(size_t)(k0 + i) * N + n0 + tx];
    __syncthreads();
    #pragma unroll
    for (int i = ty; i < 32; i += 8)
        T[(size_t)(n0 + i) * K + k0 + tx] = __float2half_rn(t[tx][i]);
}

// ---------------------------------------------------------------------------
// fp16 GEMM:  out[M,N] = A[M,K] @ B[N,K]^T   (1 MMA / frag)  [verified R8]
// CTA 128x128, 8 warps, K-chunk 64, 3-stage cp.async, 2 CTAs/SM.
// EPI: 0 bias->f32, 1 bias+res->f32, 2 bias+GELU->fp16,
//      3 bias(seg-select)->fp16 packed (QKV, N=3072)
// ---------------------------------------------------------------------------
#define TSTRIDE 144
#define TILE_B  (128 * TSTRIDE)       // 18432 B
#define STAGE_B (2 * TILE_B)          // A, B => 36864 B
#define GSMEM   (3 * STAGE_B)         // 110592 B

__device__ __forceinline__ void load_chunk2(
    uint32_t sstage, const __half* __restrict__ A,
    const __half* __restrict__ B, int bm, int bn, int k0, int K, int tid)
{
    const int rsub = tid >> 3;
    const int seg  = tid & 7;
    #pragma unroll
    for (int i = 0; i < 8; i++) {
        const int t2  = i >> 2;
        const int row = (i & 3) * 32 + rsub;
        const __half* sp = t2 ? B : A;
        const int gr = (t2 ? bn : bm) + row;
        cpasync16(sstage + t2 * TILE_B + row * TSTRIDE + seg * 16,
                  sp + (size_t)gr * K + k0 + seg * 8);
    }
}

template <int EPI>
__global__ __launch_bounds__(256, 2) void mma_gemm(
    const __half* __restrict__ A, const __half* __restrict__ B,
    const float* __restrict__ bias, const float* __restrict__ bias2,
    const float* __restrict__ bias3, const float* __restrict__ res,
    float* __restrict__ outF, __half* __restrict__ outH, int K, int N)
{
    extern __shared__ char smem[];
    const uint32_t sbase = smem_u32(smem);

    const int tid  = threadIdx.x;
    const int lane = tid & 31;
    const int wid  = tid >> 5;
    const int wm   = wid >> 2;
    const int wn   = wid & 3;
    const int bm   = blockIdx.y * 128;
    const int bn   = blockIdx.x * 128;

    float acc[4][4][4];
    #pragma unroll
    for (int i = 0; i < 4; i++)
        #pragma unroll
        for (int j = 0; j < 4; j++)
            #pragma unroll
            for (int q = 0; q < 4; q++) acc[i][j][q] = 0.f;

    const int a_row = wm * 64 + (lane & 15);
    const int a_cb  = (lane >> 4) * 16;
    const int b_row = wn * 32 + (lane & 7);
    const int b_cb  = ((lane >> 3) & 1) * 16;

    const int NC = K >> 6;
    load_chunk2(sbase,           A, B, bm, bn,  0, K, tid); CP_COMMIT();
    load_chunk2(sbase + STAGE_B, A, B, bm, bn, 64, K, tid); CP_COMMIT();

    int cs = 0, ps = 2;
    for (int c = 0; c < NC; c++) {
        CP_WAIT(1);
        __syncthreads();

        const uint32_t st = sbase + cs * STAGE_B;
        const uint32_t aA = st + a_row * TSTRIDE + a_cb;
        const uint32_t aB = st + TILE_B + b_row * TSTRIDE + b_cb;

        #pragma unroll
        for (int ks = 0; ks < 4; ks++) {
            uint32_t af[4][4], bf[4][2];
            #pragma unroll
            for (int mt = 0; mt < 4; mt++)
                ldmA(af[mt], aA + mt * (16 * TSTRIDE) + ks * 32);
            #pragma unroll
            for (int nt = 0; nt < 4; nt++)
                ldmB(bf[nt], aB + nt * (8 * TSTRIDE) + ks * 32);
            #pragma unroll
            for (int mt = 0; mt < 4; mt++)
                #pragma unroll
                for (int nt = 0; nt < 4; nt++)
                    mmaF16(acc[mt][nt], af[mt], bf[nt]);
        }

        if (c + 2 < NC)
            load_chunk2(sbase + ps * STAGE_B, A, B, bm, bn, (c + 2) << 6,
                        K, tid);
        CP_COMMIT();
        cs = (cs == 2) ? 0 : cs + 1;
        ps = (ps == 2) ? 0 : ps + 1;
    }

    // epilogue
    const float* bp = bias;
    int bofs = 0;
    if (EPI == 3) {
        bp   = (bn < 1024) ? bias : (bn < 2048) ? bias2 : bias3;
        bofs = bn & ~1023;
    }
    const int r0 = bm + wm * 64 + (lane >> 2);
    const int c0 = bn + wn * 32 + 2 * (lane & 3);
    #pragma unroll
    for (int mt = 0; mt < 4; mt++) {
        #pragma unroll
        for (int nt = 0; nt < 4; nt++) {
            const int col = c0 + nt * 8;
            const float2 bb = *(const float2*)(bp + col - bofs);
            #pragma unroll
            for (int half = 0; half < 2; half++) {
                const int row = r0 + mt * 16 + half * 8;
                const size_t off = (size_t)row * N + col;
                float v0 = acc[mt][nt][half * 2 + 0] + bb.x;
                float v1 = acc[mt][nt][half * 2 + 1] + bb.y;
                if (EPI == 1) {
                    const float2 rr = *(const float2*)(res + off);
                    v0 += rr.x; v1 += rr.y;
                }
                if (EPI == 2) {
                    v0 = gelu_exact(v0); v1 = gelu_exact(v1);
                    *(uint32_t*)(outH + off) = pack_f16(v0, v1);
                } else if (EPI == 3) {
                    *(uint32_t*)(outH + off) = pack_f16(v0, v1);
                } else {
                    float2 o; o.x = v0; o.y = v1;
                    *(float2*)(outF + off) = o;
                }
            }
        }
    }
}

// ---------------------------------------------------------------------------
// fp16 mma flash attention. Grid (SEQ/128, B*H), 256 thr.
// R10: K/V fragment loads via ldmatrix.x4 (2 fragment pairs / LDSM).
// ---------------------------------------------------------------------------
#define AK_OFF    18432
#define AV_OFF    36864
#define AKV_STAGE 9216
#define ASMEM     55296

__device__ __forceinline__ void attn_load_kv(
    uint32_t sb, const __half* __restrict__ qkv, int rowKV, int hoff,
    int stage, int kt, int tid)
{
    const int rb = rowKV + kt * 64;
    #pragma unroll
    for (int i = 0; i < 4; i++) {
        const int idx  = i * 256 + tid;
        const int half = idx >> 9;
        const int r    = (idx >> 3) & 63;
        const int seg  = idx & 7;
        const int coff = (half ? 2048 : 1024) + hoff;
        const uint32_t dst = sb + (half ? AV_OFF : AK_OFF) +
                             stage * AKV_STAGE + r * 144 + seg * 16;
        cpasync16(dst, qkv + (size_t)(rb + r) * QKV_ST + coff + seg * 8);
    }
}

__global__ __launch_bounds__(256, 2) void attn_mma(
    const __half* __restrict__ qkv, __half* __restrict__ Oh)
{
    extern __shared__ char smem[];
    const uint32_t sb = smem_u32(smem);
    const int tid = threadIdx.x, lane = tid & 31, wid = tid >> 5;
    const int qt   = blockIdx.x;
    const int b    = blockIdx.y >> 4, h = blockIdx.y & 15;
    const int rowQ  = b * SEQLEN + qt * 128;
    const int rowKV = b * SEQLEN;
    const int hoff  = h * HDIM;

    #pragma unroll
    for (int i = 0; i < 4; i++) {
        const int idx = i * 256 + tid;
        const int r = idx >> 3, seg = idx & 7;
        cpasync16(sb + r * 144 + seg * 16,
                  qkv + (size_t)(rowQ + r) * QKV_ST + hoff + seg * 8);
    }
    attn_load_kv(sb, qkv, rowKV, hoff, 0, 0, tid);
    CP_COMMIT();
    attn_load_kv(sb, qkv, rowKV, hoff, 1, 1, tid);
    CP_COMMIT();

    CP_WAIT(1);
    __syncthreads();

    uint32_t qf[4][4];
    {
        const uint32_t qa = sb + (wid * 16 + (lane & 15)) * 144 +
                            (lane >> 4) * 16;
        #pragma unroll
        for (int ks = 0; ks < 4; ks++) ldmA(qf[ks], qa + ks * 32);
    }

    float o[8][4];
    #pragma unroll
    for (int nt = 0; nt < 8; nt++)
        #pragma unroll
        for (int j = 0; j < 4; j++) o[nt][j] = 0.f;
    float mrun[2] = {-1e30f, -1e30f}, lrun[2] = {0.f, 0.f};

    // x4 K loads: lanes 0-7 -> tile(nt2*2, k-lo), 8-15 -> (nt2*2, k-hi),
    //             16-23 -> (nt2*2+1, k-lo), 24-31 -> (nt2*2+1, k-hi)
    const uint32_t koff4 = (lane & 7) * 144 + ((lane >> 3) & 1) * 16 +
                           ((lane >> 4) & 1) * (8 * 144);
    // x4.trans V loads: lane i -> V row (tp*32 + i); matrices = k-halves of
    // two consecutive 16-row groups.
    const uint32_t voff4 = (lane & 31) * 144;
    constexpr int NKT = SEQLEN / 64;

    for (int kt = 0; kt < NKT; kt++) {
        if (kt > 0) {
            if (kt + 1 < NKT) { CP_WAIT(1); } else { CP_WAIT(0); }
            __syncthreads();
        }
        const int stage = kt & 1;
        const uint32_t skb = sb + AK_OFF + stage * AKV_STAGE;
        const uint32_t svb = sb + AV_OFF + stage * AKV_STAGE;

        float sacc[8][4];
        #pragma unroll
        for (int nt = 0; nt < 8; nt++)
            #pragma unroll
            for (int j = 0; j < 4; j++) sacc[nt][j] = 0.f;
        #pragma unroll
        for (int ks = 0; ks < 4; ks++) {
            #pragma unroll
            for (int nt2 = 0; nt2 < 4; nt2++) {
                uint32_t kf4[4];
                ldmA(kf4, skb + nt2 * (16 * 144) + koff4 + ks * 32);
                mmaF16(sacc[2 * nt2 + 0], qf[ks], kf4 + 0);
                mmaF16(sacc[2 * nt2 + 1], qf[ks], kf4 + 2);
            }
        }

        float corr[2];
        #pragma unroll
        for (int hf = 0; hf < 2; hf++) {
            const int i0 = hf * 2, i1 = hf * 2 + 1;
            float mx = fmaxf(sacc[0][i0], sacc[0][i1]);
            #pragma unroll
            for (int nt = 1; nt < 8; nt++)
                mx = fmaxf(mx, fmaxf(sacc[nt][i0], sacc[nt][i1]));
            mx = fmaxf(mx, __shfl_xor_sync(0xffffffffu, mx, 1));
            mx = fmaxf(mx, __shfl_xor_sync(0xffffffffu, mx, 2));
            const float mn = fmaxf(mrun[hf], mx);
            const float cm = C_SCALE * mn;
            corr[hf] = exp2_fast(fmaf(C_SCALE, mrun[hf], -cm));
            float sum = 0.f;
            #pragma unroll
            for (int nt = 0; nt < 8; nt++) {
                const float p0 = exp2_fast(fmaf(sacc[nt][i0], C_SCALE, -cm));
                const float p1 = exp2_fast(fmaf(sacc[nt][i1], C_SCALE, -cm));
                sacc[nt][i0] = p0; sacc[nt][i1] = p1;
                sum += p0 + p1;
            }
            sum += __shfl_xor_sync(0xffffffffu, sum, 1);
            sum += __shfl_xor_sync(0xffffffffu, sum, 2);
            lrun[hf] = lrun[hf] * corr[hf] + sum;
            mrun[hf] = mn;
        }

        uint32_t pa[4][4];
        #pragma unroll
        for (int t = 0; t < 4; t++) {
            pa[t][0] = pack_f16(sacc[2 * t][0],     sacc[2 * t][1]);
            pa[t][1] = pack_f16(sacc[2 * t][2],     sacc[2 * t][3]);
            pa[t][2] = pack_f16(sacc[2 * t + 1][0], sacc[2 * t + 1][1]);
            pa[t][3] = pack_f16(sacc[2 * t + 1][2], sacc[2 * t + 1][3]);
        }

        #pragma unroll
        for (int nt = 0; nt < 8; nt++) {
            o[nt][0] *= corr[0]; o[nt][1] *= corr[0];
            o[nt][2] *= corr[1]; o[nt][3] *= corr[1];
        }
        #pragma unroll
        for (int tp = 0; tp < 2; tp++) {
            #pragma unroll
            for (int nt = 0; nt < 8; nt++) {
                uint32_t vf4[4];
                ldmAT(vf4, svb + tp * (32 * 144) + voff4 + nt * 16);
                mmaF16(o[nt], pa[2 * tp + 0], vf4 + 0);
                mmaF16(o[nt], pa[2 * tp + 1], vf4 + 2);
            }
        }

        __syncthreads();
        if (kt + 2 < NKT) {
            attn_load_kv(sb, qkv, rowKV, hoff, stage, kt + 2, tid);
            CP_COMMIT();
        }
    }

    const float inv0 = 1.0f / lrun[0], inv1 = 1.0f / lrun[1];
    const int rg = rowQ + wid * 16 + (lane >> 2);
    const int cg = hoff + 2 * (lane & 3);
    #pragma unroll
    for (int nt = 0; nt < 8; nt++) {
        #pragma unroll
        for (int hf = 0; hf < 2; hf++) {
            const float inv = hf ? inv1 : inv0;
            const size_t off = (size_t)(rg + hf * 8) * CDIM + cg + nt * 8;
            *(uint32_t*)(Oh + off) =
                pack_f16(o[nt][hf * 2 + 0] * inv, o[nt][hf * 2 + 1] * inv);
        }
    }
}

// ---------------------------------------------------------------------------
// kernel_launch — weight prep forked onto a side stream (captured fork/join)
// ---------------------------------------------------------------------------
extern "C" void kernel_launch(void* const* d_in, const int* in_sizes, int n_in,
                              void* d_out, int out_size)
{
    const float* x   = (const float*)d_in[0];
    const float* g1  = (const float*)d_in[1];
    const float* b1  = (const float*)d_in[2];
    const float* Wq  = (const float*)d_in[3];
    const float* bq  = (const float*)d_in[4];
    const float* Wk  = (const float*)d_in[5];
    const float* bk  = (const float*)d_in[6];
    const float* Wv  = (const float*)d_in[7];
    const float* bv  = (const float*)d_in[8];
    const float* Wo  = (const float*)d_in[9];
    const float* bo  = (const float*)d_in[10];
    const float* g2  = (const float*)d_in[11];
    const float* b2  = (const float*)d_in[12];
    const float* W1  = (const float*)d_in[13];
    const float* bf1 = (const float*)d_in[14];
    const float* W2  = (const float*)d_in[15];
    const float* bf2 = (const float*)d_in[16];
    float* out = (float*)d_out;

    float *px1;
    __half *ph, *pqkv, *po, *pf, *pwqkv, *pwo, *pw1t, *pw2t;
    cudaGetSymbolAddress((void**)&px1,   g_x1);
    cudaGetSymbolAddress((void**)&ph,    g_h);
    cudaGetSymbolAddress((void**)&pqkv,  g_qkv);
    cudaGetSymbolAddress((void**)&po,    g_o);
    cudaGetSymbolAddress((void**)&pf,    g_f);
    cudaGetSymbolAddress((void**)&pwqkv, g_wqkv);
    cudaGetSymbolAddress((void**)&pwo,   g_wo);
    cudaGetSymbolAddress((void**)&pw1t,  g_w1t);
    cudaGetSymbolAddress((void**)&pw2t,  g_w2t);

    cudaFuncSetAttribute(mma_gemm<1>, cudaFuncAttributeMaxDynamicSharedMemorySize, GSMEM);
    cudaFuncSetAttribute(mma_gemm<2>, cudaFuncAttributeMaxDynamicSharedMemorySize, GSMEM);
    cudaFuncSetAttribute(mma_gemm<3>, cudaFuncAttributeMaxDynamicSharedMemorySize, GSMEM);
    cudaFuncSetAttribute(attn_mma,    cudaFuncAttributeMaxDynamicSharedMemorySize, ASMEM);

    static cudaStream_t s1 = nullptr;
    static cudaEvent_t evF = nullptr, evA = nullptr, evB = nullptr;
    if (!s1) {
        cudaStreamCreateWithFlags(&s1, cudaStreamNonBlocking);
        cudaEventCreateWithFlags(&evF, cudaEventDisableTiming);
        cudaEventCreateWithFlags(&evA, cudaEventDisableTiming);
        cudaEventCreateWithFlags(&evB, cudaEventDisableTiming);
    }

    const dim3 gQKV(QKV_ST / 128, MTOT / 128);   // (24, 32)
    const dim3 gP  (CDIM / 128,   MTOT / 128);   // (8, 32)
    const dim3 gF1 (HIDDIM / 128, MTOT / 128);   // (32, 32)

    // ---- fork: weight prep on s1 ----
    cudaEventRecord(evF, 0);
    cudaStreamWaitEvent(s1, evF, 0);
    wtrans4_kernel<<<dim3(32, 32, 4), 256, 0, s1>>>(Wq, Wk, Wv, Wo, pwqkv, pwo);
    cudaEventRecord(evA, s1);                        // QKV/Wo weights ready
    wtrans_kernel<<<dim3(HIDDIM / 32, CDIM / 32), 256, 0, s1>>>(
        W1, pw1t, CDIM, HIDDIM);
    wtrans_kernel<<<dim3(CDIM / 32, HIDDIM / 32), 256, 0, s1>>>(
        W2, pw2t, HIDDIM, CDIM);
    cudaEventRecord(evB, s1);                        // FFN weights ready

    // ---- main chain ----
    ln_kernel<<<MTOT / 4, 256>>>(x, g1, b1, ph);                  // LN1
    cudaStreamWaitEvent(0, evA, 0);
    mma_gemm<3><<<gQKV, 256, GSMEM>>>(ph, pwqkv, bq, bk, bv, nullptr,
                                      nullptr, pqkv, CDIM, QKV_ST);
    attn_mma<<<dim3(SEQLEN / 128, NBATCH * NHEADS), 256, ASMEM>>>(pqkv, po);
    mma_gemm<1><<<gP, 256, GSMEM>>>(po, pwo, bo, nullptr, nullptr, x,
                                    px1, nullptr, CDIM, CDIM);    // Wo + res
    ln_kernel<<<MTOT / 4, 256>>>(px1, g2, b2, ph);                // LN2
    cudaStreamWaitEvent(0, evB, 0);
    mma_gemm<2><<<gF1, 256, GSMEM>>>(ph, pw1t, bf1, nullptr, nullptr, nullptr,
                                     nullptr, pf, CDIM, HIDDIM);  // FFN1+GELU
    mma_gemm<1><<<gP, 256, GSMEM>>>(pf, pw2t, bf2, nullptr, nullptr, px1,
                                    out, nullptr, HIDDIM, CDIM);  // FFN2 + res
}

// round 12
// speedup vs baseline: 1.0709x; 1.0709x over previous
#include <cuda_runtime.h>
#include <cuda_fp16.h>
#include <math.h>
#include <stdint.h>

// ---------------------------------------------------------------------------
// TransformerBlock on GB300 (sm_103a; PTX target compute_103 => portable
// features only: mma.sync / ldmatrix / cp.async).
// Round 11: dual batch-pipeline. Evidence: R10 micro-opts were neutral =>
// the ~90us over the 418us compute floor is wave quantization + serialization
// (QKV 2.59 waves, attn 1.73, FFN1 3.46, Wo/FFN2 underfilled single waves).
// Fix: the block is row-separable by batch => run batch 0 and batch 1 as two
// independent kernel chains on two streams; every tail overlaps the other
// chain's head. Kernels themselves are the verified R10 versions.
// ---------------------------------------------------------------------------

#define MTOT   4096
#define CDIM   1024
#define HIDDIM 4096
#define NBATCH 2
#define SEQLEN 2048
#define NHEADS 16
#define HDIM   64
#define QKV_ST 3072
#define HROWS  2048                      // rows per batch half

// ------------------------------ scratch ------------------------------------
__device__ float  g_x1[MTOT * CDIM];
__device__ __half g_h  [MTOT * CDIM];                        // LN out fp16
__device__ __half g_qkv[(size_t)MTOT * QKV_ST];              // packed Q|K|V
__device__ __half g_o  [MTOT * CDIM];                        // attn out fp16
__device__ __half g_f  [(size_t)MTOT * HIDDIM];              // FFN hidden fp16
__device__ __half g_wqkv[(size_t)3 * CDIM * CDIM];           // W^T packed qkv
__device__ __half g_wo [(size_t)CDIM * CDIM];
__device__ __half g_w1t[(size_t)HIDDIM * CDIM];
__device__ __half g_w2t[(size_t)CDIM * HIDDIM];

// --------------------------- helpers ---------------------------------------
__device__ __forceinline__ uint32_t smem_u32(const void* p) {
    uint32_t a;
    asm("{ .reg .u64 t; cvta.to.shared.u64 t, %1; cvt.u32.u64 %0, t; }"
        : "=r"(a) : "l"(p));
    return a;
}
__device__ __forceinline__ void cpasync16(uint32_t saddr, const void* g) {
    asm volatile("cp.async.cg.shared.global [%0], [%1], 16;"
                 :: "r"(saddr), "l"(g));
}
#define CP_COMMIT() asm volatile("cp.async.commit_group;" ::: "memory")
#define CP_WAIT(n)  asm volatile("cp.async.wait_group %0;" :: "n"(n) : "memory")

__device__ __forceinline__ void ldmA(uint32_t* a, uint32_t addr) {
    asm volatile("ldmatrix.sync.aligned.m8n8.x4.shared.b16 {%0,%1,%2,%3}, [%4];"
        : "=r"(a[0]), "=r"(a[1]), "=r"(a[2]), "=r"(a[3]) : "r"(addr));
}
__device__ __forceinline__ void ldmAT(uint32_t* a, uint32_t addr) {
    asm volatile("ldmatrix.sync.aligned.m8n8.x4.trans.shared.b16 {%0,%1,%2,%3}, [%4];"
        : "=r"(a[0]), "=r"(a[1]), "=r"(a[2]), "=r"(a[3]) : "r"(addr));
}
__device__ __forceinline__ void ldmB(uint32_t* b, uint32_t addr) {
    asm volatile("ldmatrix.sync.aligned.m8n8.x2.shared.b16 {%0,%1}, [%2];"
        : "=r"(b[0]), "=r"(b[1]) : "r"(addr));
}
__device__ __forceinline__ void mmaF16(float* d, const uint32_t* a,
                                       const uint32_t* b) {
    asm volatile(
        "mma.sync.aligned.m16n8k16.row.col.f32.f16.f16.f32 "
        "{%0,%1,%2,%3}, {%4,%5,%6,%7}, {%8,%9}, {%0,%1,%2,%3};"
        : "+f"(d[0]), "+f"(d[1]), "+f"(d[2]), "+f"(d[3])
        : "r"(a[0]), "r"(a[1]), "r"(a[2]), "r"(a[3]), "r"(b[0]), "r"(b[1]));
}
__device__ __forceinline__ uint32_t pack_f16(float lo, float hi) {
    uint32_t r;
    asm("cvt.rn.f16x2.f32 %0, %1, %2;" : "=r"(r) : "f"(hi), "f"(lo));
    return r;
}
__device__ __forceinline__ float gelu_exact(float x) {
    return 0.5f * x * (1.0f + erff(x * 0.70710678118654752f));
}
// FMA-pipe 2^x (no MUFU).
__device__ __forceinline__ float exp2_fast(float x) {
    x = fmaxf(x, -126.0f);
    const float z = x + 12582912.0f;
    const int   i = __float_as_int(z) - 0x4B400000;
    const float f = x - (z - 12582912.0f);
    float p =          1.3333558e-3f;
    p = fmaf(p, f, 9.6181291e-3f);
    p = fmaf(p, f, 5.5504109e-2f);
    p = fmaf(p, f, 2.4022651e-1f);
    p = fmaf(p, f, 6.9314718e-1f);
    p = fmaf(p, f, 1.0f);
    return __int_as_float(__float_as_int(p) + (i << 23));
}
#define C_SCALE 0.18033688f   // (1/sqrt(64)) * log2(e)

// ---------------------------------------------------------------------------
// LayerNorm -> fp16. 2 warps per row, 4 float4/thread. Block 256 = 4 rows.
// ---------------------------------------------------------------------------
__global__ __launch_bounds__(256) void ln_kernel(
    const float* __restrict__ in, const float* __restrict__ gamma,
    const float* __restrict__ beta, __half* __restrict__ oh)
{
    const int tid  = threadIdx.x;
    const int rloc = tid >> 6;
    const int sub  = tid & 63;
    const int row  = blockIdx.x * 4 + rloc;
    const float4* rp = (const float4*)(in + (size_t)row * CDIM);

    float4 v[4];
    #pragma unroll
    for (int i = 0; i < 4; i++) v[i] = rp[sub + 64 * i];

    float s = 0.f, ss = 0.f;
    #pragma unroll
    for (int i = 0; i < 4; i++) {
        s  += v[i].x + v[i].y + v[i].z + v[i].w;
        ss += v[i].x * v[i].x + v[i].y * v[i].y +
              v[i].z * v[i].z + v[i].w * v[i].w;
    }
    #pragma unroll
    for (int o = 16; o > 0; o >>= 1) {
        s  += __shfl_xor_sync(0xffffffffu, s,  o);
        ss += __shfl_xor_sync(0xffffffffu, ss, o);
    }
    __shared__ float2 part[8];
    const int w = tid >> 5;
    if ((tid & 31) == 0) { part[w].x = s; part[w].y = ss; }
    __syncthreads();
    const float2 pa = part[rloc * 2 + 0];
    const float2 pb = part[rloc * 2 + 1];
    const float mu = (pa.x + pb.x) * (1.0f / CDIM);
    const float r  = rsqrtf((pa.y + pb.y) * (1.0f / CDIM) - mu * mu + 1e-5f);

    uint2* op = (uint2*)(oh + (size_t)row * CDIM);
    #pragma unroll
    for (int i = 0; i < 4; i++) {
        const float4 g4 = ((const float4*)gamma)[sub + 64 * i];
        const float4 b4 = ((const float4*)beta )[sub + 64 * i];
        uint2 o;
        o.x = pack_f16((v[i].x - mu) * r * g4.x + b4.x,
                       (v[i].y - mu) * r * g4.y + b4.y);
        o.y = pack_f16((v[i].z - mu) * r * g4.z + b4.z,
                       (v[i].w - mu) * r * g4.w + b4.w);
        op[sub + 64 * i] = o;
    }
}

// ---------------------------------------------------------------------------
// Weight transposes -> fp16 (prep stream).
// ---------------------------------------------------------------------------
__global__ __launch_bounds__(256) void wtrans4_kernel(
    const float* __restrict__ Wq, const float* __restrict__ Wk,
    const float* __restrict__ Wv, const float* __restrict__ Wo,
    __half* __restrict__ wqkv, __half* __restrict__ wo)
{
    __shared__ float t[32][33];
    const int z  = blockIdx.z;
    const float* W = (z == 0) ? Wq : (z == 1) ? Wk : (z == 2) ? Wv : Wo;
    __half* T = (z < 3) ? (wqkv + (size_t)z * CDIM * CDIM) : wo;
    const int n0 = blockIdx.x * 32, k0 = blockIdx.y * 32;
    const int tx = threadIdx.x & 31, ty = threadIdx.x >> 5;
    #pragma unroll
    for (int i = ty; i < 32; i += 8)
        t[i][tx] = W[(size_t)(k0 + i) * CDIM + n0 + tx];
    __syncthreads();
    #pragma unroll
    for (int i = ty; i < 32; i += 8)
        T[(size_t)(n0 + i) * CDIM + k0 + tx] = __float2half_rn(t[tx][i]);
}

__global__ __launch_bounds__(256) void wtrans_kernel(
    const float* __restrict__ W, __half* __restrict__ T, int K, int N)
{
    __shared__ float t[32][33];
    const int n0 = blockIdx.x * 32, k0 = blockIdx.y * 32;
    const int tx = threadIdx.x & 31, ty = threadIdx.x >> 5;
    #pragma unroll
    for (int i = ty; i < 32; i += 8)
        t[i][tx] = W[(size_t)(k0 + i) * N + n0 + tx];
    __syncthreads();
    #pragma unroll
    for (int i = ty; i < 32; i += 8)
        T[(size_t)(n0 + i) * K + k0 + tx] = __float2half_rn(t[tx][i]);
}

// ---------------------------------------------------------------------------
// fp16 GEMM:  out[M,N] = A[M,K] @ B[N,K]^T   (1 MMA / frag)  [verified R8]
// Pointers pre-offset per batch half; grid.y covers the half's M tiles.
// EPI: 0 bias->f32, 1 bias+res->f32, 2 bias+GELU->fp16,
//      3 bias(seg-select)->fp16 packed (QKV, N=3072)
// ---------------------------------------------------------------------------
#define TSTRIDE 144
#define TILE_B  (128 * TSTRIDE)       // 18432 B
#define STAGE_B (2 * TILE_B)          // A, B => 36864 B
#define GSMEM   (3 * STAGE_B)         // 110592 B

__device__ __forceinline__ void load_chunk2(
    uint32_t sstage, const __half* __restrict__ A,
    const __half* __restrict__ B, int bm, int bn, int k0, int K, int tid)
{
    const int rsub = tid >> 3;
    const int seg  = tid & 7;
    #pragma unroll
    for (int i = 0; i < 8; i++) {
        const int t2  = i >> 2;
        const int row = (i & 3) * 32 + rsub;
        const __half* sp = t2 ? B : A;
        const int gr = (t2 ? bn : bm) + row;
        cpasync16(sstage + t2 * TILE_B + row * TSTRIDE + seg * 16,
                  sp + (size_t)gr * K + k0 + seg * 8);
    }
}

template <int EPI>
__global__ __launch_bounds__(256, 2) void mma_gemm(
    const __half* __restrict__ A, const __half* __restrict__ B,
    const float* __restrict__ bias, const float* __restrict__ bias2,
    const float* __restrict__ bias3, const float* __restrict__ res,
    float* __restrict__ outF, __half* __restrict__ outH, int K, int N)
{
    extern __shared__ char smem[];
    const uint32_t sbase = smem_u32(smem);

    const int tid  = threadIdx.x;
    const int lane = tid & 31;
    const int wid  = tid >> 5;
    const int wm   = wid >> 2;
    const int wn   = wid & 3;
    const int bm   = blockIdx.y * 128;
    const int bn   = blockIdx.x * 128;

    float acc[4][4][4];
    #pragma unroll
    for (int i = 0; i < 4; i++)
        #pragma unroll
        for (int j = 0; j < 4; j++)
            #pragma unroll
            for (int q = 0; q < 4; q++) acc[i][j][q] = 0.f;

    const int a_row = wm * 64 + (lane & 15);
    const int a_cb  = (lane >> 4) * 16;
    const int b_row = wn * 32 + (lane & 7);
    const int b_cb  = ((lane >> 3) & 1) * 16;

    const int NC = K >> 6;
    load_chunk2(sbase,           A, B, bm, bn,  0, K, tid); CP_COMMIT();
    load_chunk2(sbase + STAGE_B, A, B, bm, bn, 64, K, tid); CP_COMMIT();

    int cs = 0, ps = 2;
    for (int c = 0; c < NC; c++) {
        CP_WAIT(1);
        __syncthreads();

        const uint32_t st = sbase + cs * STAGE_B;
        const uint32_t aA = st + a_row * TSTRIDE + a_cb;
        const uint32_t aB = st + TILE_B + b_row * TSTRIDE + b_cb;

        #pragma unroll
        for (int ks = 0; ks < 4; ks++) {
            uint32_t af[4][4], bf[4][2];
            #pragma unroll
            for (int mt = 0; mt < 4; mt++)
                ldmA(af[mt], aA + mt * (16 * TSTRIDE) + ks * 32);
            #pragma unroll
            for (int nt = 0; nt < 4; nt++)
                ldmB(bf[nt], aB + nt * (8 * TSTRIDE) + ks * 32);
            #pragma unroll
            for (int mt = 0; mt < 4; mt++)
                #pragma unroll
                for (int nt = 0; nt < 4; nt++)
                    mmaF16(acc[mt][nt], af[mt], bf[nt]);
        }

        if (c + 2 < NC)
            load_chunk2(sbase + ps * STAGE_B, A, B, bm, bn, (c + 2) << 6,
                        K, tid);
        CP_COMMIT();
        cs = (cs == 2) ? 0 : cs + 1;
        ps = (ps == 2) ? 0 : ps + 1;
    }

    // epilogue
    const float* bp = bias;
    int bofs = 0;
    if (EPI == 3) {
        bp   = (bn < 1024) ? bias : (bn < 2048) ? bias2 : bias3;
        bofs = bn & ~1023;
    }
    const int r0 = bm + wm * 64 + (lane >> 2);
    const int c0 = bn + wn * 32 + 2 * (lane & 3);
    #pragma unroll
    for (int mt = 0; mt < 4; mt++) {
        #pragma unroll
        for (int nt = 0; nt < 4; nt++) {
            const int col = c0 + nt * 8;
            const float2 bb = *(const float2*)(bp + col - bofs);
            #pragma unroll
            for (int half = 0; half < 2; half++) {
                const int row = r0 + mt * 16 + half * 8;
                const size_t off = (size_t)row * N + col;
                float v0 = acc[mt][nt][half * 2 + 0] + bb.x;
                float v1 = acc[mt][nt][half * 2 + 1] + bb.y;
                if (EPI == 1) {
                    const float2 rr = *(const float2*)(res + off);
                    v0 += rr.x; v1 += rr.y;
                }
                if (EPI == 2) {
                    v0 = gelu_exact(v0); v1 = gelu_exact(v1);
                    *(uint32_t*)(outH + off) = pack_f16(v0, v1);
                } else if (EPI == 3) {
                    *(uint32_t*)(outH + off) = pack_f16(v0, v1);
                } else {
                    float2 o; o.x = v0; o.y = v1;
                    *(float2*)(outF + off) = o;
                }
            }
        }
    }
}

// ---------------------------------------------------------------------------
// fp16 mma flash attention [verified R10]. One batch per launch:
// qkv/Oh pre-offset; grid (SEQ/128, NHEADS), blockIdx.y = head.
// ---------------------------------------------------------------------------
#define AK_OFF    18432
#define AV_OFF    36864
#define AKV_STAGE 9216
#define ASMEM     55296

__device__ __forceinline__ void attn_load_kv(
    uint32_t sb, const __half* __restrict__ qkv, int hoff,
    int stage, int kt, int tid)
{
    const int rb = kt * 64;
    #pragma unroll
    for (int i = 0; i < 4; i++) {
        const int idx  = i * 256 + tid;
        const int half = idx >> 9;
        const int r    = (idx >> 3) & 63;
        const int seg  = idx & 7;
        const int coff = (half ? 2048 : 1024) + hoff;
        const uint32_t dst = sb + (half ? AV_OFF : AK_OFF) +
                             stage * AKV_STAGE + r * 144 + seg * 16;
        cpasync16(dst, qkv + (size_t)(rb + r) * QKV_ST + coff + seg * 8);
    }
}

__global__ __launch_bounds__(256, 2) void attn_mma(
    const __half* __restrict__ qkv, __half* __restrict__ Oh)
{
    extern __shared__ char smem[];
    const uint32_t sb = smem_u32(smem);
    const int tid = threadIdx.x, lane = tid & 31, wid = tid >> 5;
    const int qt   = blockIdx.x;
    const int h    = blockIdx.y;
    const int rowQ = qt * 128;
    const int hoff = h * HDIM;

    #pragma unroll
    for (int i = 0; i < 4; i++) {
        const int idx = i * 256 + tid;
        const int r = idx >> 3, seg = idx & 7;
        cpasync16(sb + r * 144 + seg * 16,
                  qkv + (size_t)(rowQ + r) * QKV_ST + hoff + seg * 8);
    }
    attn_load_kv(sb, qkv, hoff, 0, 0, tid);
    CP_COMMIT();
    attn_load_kv(sb, qkv, hoff, 1, 1, tid);
    CP_COMMIT();

    CP_WAIT(1);
    __syncthreads();

    uint32_t qf[4][4];
    {
        const uint32_t qa = sb + (wid * 16 + (lane & 15)) * 144 +
                            (lane >> 4) * 16;
        #pragma unroll
        for (int ks = 0; ks < 4; ks++) ldmA(qf[ks], qa + ks * 32);
    }

    float o[8][4];
    #pragma unroll
    for (int nt = 0; nt < 8; nt++)
        #pragma unroll
        for (int j = 0; j < 4; j++) o[nt][j] = 0.f;
    float mrun[2] = {-1e30f, -1e30f}, lrun[2] = {0.f, 0.f};

    const uint32_t koff4 = (lane & 7) * 144 + ((lane >> 3) & 1) * 16 +
                           ((lane >> 4) & 1) * (8 * 144);
    const uint32_t voff4 = (lane & 31) * 144;
    constexpr int NKT = SEQLEN / 64;

    for (int kt = 0; kt < NKT; kt++) {
        if (kt > 0) {
            if (kt + 1 < NKT) { CP_WAIT(1); } else { CP_WAIT(0); }
            __syncthreads();
        }
        const int stage = kt & 1;
        const uint32_t skb = sb + AK_OFF + stage * AKV_STAGE;
        const uint32_t svb = sb + AV_OFF + stage * AKV_STAGE;

        float sacc[8][4];
        #pragma unroll
        for (int nt = 0; nt < 8; nt++)
            #pragma unroll
            for (int j = 0; j < 4; j++) sacc[nt][j] = 0.f;
        #pragma unroll
        for (int ks = 0; ks < 4; ks++) {
            #pragma unroll
            for (int nt2 = 0; nt2 < 4; nt2++) {
                uint32_t kf4[4];
                ldmA(kf4, skb + nt2 * (16 * 144) + koff4 + ks * 32);
                mmaF16(sacc[2 * nt2 + 0], qf[ks], kf4 + 0);
                mmaF16(sacc[2 * nt2 + 1], qf[ks], kf4 + 2);
            }
        }

        float corr[2];
        #pragma unroll
        for (int hf = 0; hf < 2; hf++) {
            const int i0 = hf * 2, i1 = hf * 2 + 1;
            float mx = fmaxf(sacc[0][i0], sacc[0][i1]);
            #pragma unroll
            for (int nt = 1; nt < 8; nt++)
                mx = fmaxf(mx, fmaxf(sacc[nt][i0], sacc[nt][i1]));
            mx = fmaxf(mx, __shfl_xor_sync(0xffffffffu, mx, 1));
            mx = fmaxf(mx, __shfl_xor_sync(0xffffffffu, mx, 2));
            const float mn = fmaxf(mrun[hf], mx);
            const float cm = C_SCALE * mn;
            corr[hf] = exp2_fast(fmaf(C_SCALE, mrun[hf], -cm));
            float sum = 0.f;
            #pragma unroll
            for (int nt = 0; nt < 8; nt++) {
                const float p0 = exp2_fast(fmaf(sacc[nt][i0], C_SCALE, -cm));
                const float p1 = exp2_fast(fmaf(sacc[nt][i1], C_SCALE, -cm));
                sacc[nt][i0] = p0; sacc[nt][i1] = p1;
                sum += p0 + p1;
            }
            sum += __shfl_xor_sync(0xffffffffu, sum, 1);
            sum += __shfl_xor_sync(0xffffffffu, sum, 2);
            lrun[hf] = lrun[hf] * corr[hf] + sum;
            mrun[hf] = mn;
        }

        uint32_t pa[4][4];
        #pragma unroll
        for (int t = 0; t < 4; t++) {
            pa[t][0] = pack_f16(sacc[2 * t][0],     sacc[2 * t][1]);
            pa[t][1] = pack_f16(sacc[2 * t][2],     sacc[2 * t][3]);
            pa[t][2] = pack_f16(sacc[2 * t + 1][0], sacc[2 * t + 1][1]);
            pa[t][3] = pack_f16(sacc[2 * t + 1][2], sacc[2 * t + 1][3]);
        }

        #pragma unroll
        for (int nt = 0; nt < 8; nt++) {
            o[nt][0] *= corr[0]; o[nt][1] *= corr[0];
            o[nt][2] *= corr[1]; o[nt][3] *= corr[1];
        }
        #pragma unroll
        for (int tp = 0; tp < 2; tp++) {
            #pragma unroll
            for (int nt = 0; nt < 8; nt++) {
                uint32_t vf4[4];
                ldmAT(vf4, svb + tp * (32 * 144) + voff4 + nt * 16);
                mmaF16(o[nt], pa[2 * tp + 0], vf4 + 0);
                mmaF16(o[nt], pa[2 * tp + 1], vf4 + 2);
            }
        }

        __syncthreads();
        if (kt + 2 < NKT) {
            attn_load_kv(sb, qkv, hoff, stage, kt + 2, tid);
            CP_COMMIT();
        }
    }

    const float inv0 = 1.0f / lrun[0], inv1 = 1.0f / lrun[1];
    const int rg = rowQ + wid * 16 + (lane >> 2);
    const int cg = hoff + 2 * (lane & 3);
    #pragma unroll
    for (int nt = 0; nt < 8; nt++) {
        #pragma unroll
        for (int hf = 0; hf < 2; hf++) {
            const float inv = hf ? inv1 : inv0;
            const size_t off = (size_t)(rg + hf * 8) * CDIM + cg + nt * 8;
            *(uint32_t*)(Oh + off) =
                pack_f16(o[nt][hf * 2 + 0] * inv, o[nt][hf * 2 + 1] * inv);
        }
    }
}

// ---------------------------------------------------------------------------
// kernel_launch — dual batch pipelines (stream0 = batch 0, s1 = batch 1),
// weight prep on s2. Captured fork/join via events.
// ---------------------------------------------------------------------------
extern "C" void kernel_launch(void* const* d_in, const int* in_sizes, int n_in,
                              void* d_out, int out_size)
{
    const float* x   = (const float*)d_in[0];
    const float* g1  = (const float*)d_in[1];
    const float* b1  = (const float*)d_in[2];
    const float* Wq  = (const float*)d_in[3];
    const float* bq  = (const float*)d_in[4];
    const float* Wk  = (const float*)d_in[5];
    const float* bk  = (const float*)d_in[6];
    const float* Wv  = (const float*)d_in[7];
    const float* bv  = (const float*)d_in[8];
    const float* Wo  = (const float*)d_in[9];
    const float* bo  = (const float*)d_in[10];
    const float* g2  = (const float*)d_in[11];
    const float* b2  = (const float*)d_in[12];
    const float* W1  = (const float*)d_in[13];
    const float* bf1 = (const float*)d_in[14];
    const float* W2  = (const float*)d_in[15];
    const float* bf2 = (const float*)d_in[16];
    float* out = (float*)d_out;

    float *px1;
    __half *ph, *pqkv, *po, *pf, *pwqkv, *pwo, *pw1t, *pw2t;
    cudaGetSymbolAddress((void**)&px1,   g_x1);
    cudaGetSymbolAddress((void**)&ph,    g_h);
    cudaGetSymbolAddress((void**)&pqkv,  g_qkv);
    cudaGetSymbolAddress((void**)&po,    g_o);
    cudaGetSymbolAddress((void**)&pf,    g_f);
    cudaGetSymbolAddress((void**)&pwqkv, g_wqkv);
    cudaGetSymbolAddress((void**)&pwo,   g_wo);
    cudaGetSymbolAddress((void**)&pw1t,  g_w1t);
    cudaGetSymbolAddress((void**)&pw2t,  g_w2t);

    cudaFuncSetAttribute(mma_gemm<1>, cudaFuncAttributeMaxDynamicSharedMemorySize, GSMEM);
    cudaFuncSetAttribute(mma_gemm<2>, cudaFuncAttributeMaxDynamicSharedMemorySize, GSMEM);
    cudaFuncSetAttribute(mma_gemm<3>, cudaFuncAttributeMaxDynamicSharedMemorySize, GSMEM);
    cudaFuncSetAttribute(attn_mma,    cudaFuncAttributeMaxDynamicSharedMemorySize, ASMEM);

    static cudaStream_t s1 = nullptr, s2 = nullptr;
    static cudaEvent_t evF = nullptr, evA = nullptr, evB = nullptr,
                       evJ = nullptr;
    if (!s1) {
        cudaStreamCreateWithFlags(&s1, cudaStreamNonBlocking);
        cudaStreamCreateWithFlags(&s2, cudaStreamNonBlocking);
        cudaEventCreateWithFlags(&evF, cudaEventDisableTiming);
        cudaEventCreateWithFlags(&evA, cudaEventDisableTiming);
        cudaEventCreateWithFlags(&evB, cudaEventDisableTiming);
        cudaEventCreateWithFlags(&evJ, cudaEventDisableTiming);
    }

    const dim3 gQKV(QKV_ST / 128,  HROWS / 128);  // (24, 16)
    const dim3 gP  (CDIM / 128,    HROWS / 128);  // (8, 16)
    const dim3 gF1 (HIDDIM / 128,  HROWS / 128);  // (32, 16)
    const dim3 gAT (SEQLEN / 128,  NHEADS);       // (16, 16)

    // per-half pointer offsets
    const size_t oC  = (size_t)HROWS * CDIM;      // fp16/fp32 C-wide
    const size_t oQ  = (size_t)HROWS * QKV_ST;
    const size_t oH  = (size_t)HROWS * HIDDIM;

    // ---- fork ----
    cudaEventRecord(evF, 0);
    cudaStreamWaitEvent(s2, evF, 0);
    cudaStreamWaitEvent(s1, evF, 0);

    // prep (s2)
    wtrans4_kernel<<<dim3(32, 32, 4), 256, 0, s2>>>(Wq, Wk, Wv, Wo, pwqkv, pwo);
    cudaEventRecord(evA, s2);
    wtrans_kernel<<<dim3(HIDDIM / 32, CDIM / 32), 256, 0, s2>>>(
        W1, pw1t, CDIM, HIDDIM);
    wtrans_kernel<<<dim3(CDIM / 32, HIDDIM / 32), 256, 0, s2>>>(
        W2, pw2t, HIDDIM, CDIM);
    cudaEventRecord(evB, s2);

    // ---- batch 1 chain (s1) ----
    ln_kernel<<<HROWS / 4, 256, 0, s1>>>(x + oC, g1, b1, ph + oC);
    cudaStreamWaitEvent(s1, evA, 0);
    mma_gemm<3><<<gQKV, 256, GSMEM, s1>>>(ph + oC, pwqkv, bq, bk, bv, nullptr,
                                          nullptr, pqkv + oQ, CDIM, QKV_ST);
    attn_mma<<<gAT, 256, ASMEM, s1>>>(pqkv + oQ, po + oC);
    mma_gemm<1><<<gP, 256, GSMEM, s1>>>(po + oC, pwo, bo, nullptr, nullptr,
                                        x + oC, px1 + oC, nullptr, CDIM, CDIM);
    ln_kernel<<<HROWS / 4, 256, 0, s1>>>(px1 + oC, g2, b2, ph + oC);
    cudaStreamWaitEvent(s1, evB, 0);
    mma_gemm<2><<<gF1, 256, GSMEM, s1>>>(ph + oC, pw1t, bf1, nullptr, nullptr,
                                         nullptr, nullptr, pf + oH,
                                         CDIM, HIDDIM);
    mma_gemm<1><<<gP, 256, GSMEM, s1>>>(pf + oH, pw2t, bf2, nullptr, nullptr,
                                        px1 + oC, out + oC, nullptr,
                                        HIDDIM, CDIM);
    cudaEventRecord(evJ, s1);

    // ---- batch 0 chain (stream 0) ----
    ln_kernel<<<HROWS / 4, 256>>>(x, g1, b1, ph);
    cudaStreamWaitEvent(0, evA, 0);
    mma_gemm<3><<<gQKV, 256, GSMEM>>>(ph, pwqkv, bq, bk, bv, nullptr,
                                      nullptr, pqkv, CDIM, QKV_ST);
    attn_mma<<<gAT, 256, ASMEM>>>(pqkv, po);
    mma_gemm<1><<<gP, 256, GSMEM>>>(po, pwo, bo, nullptr, nullptr, x,
                                    px1, nullptr, CDIM, CDIM);
    ln_kernel<<<HROWS / 4, 256>>>(px1, g2, b2, ph);
    cudaStreamWaitEvent(0, evB, 0);
    mma_gemm<2><<<gF1, 256, GSMEM>>>(ph, pw1t, bf1, nullptr, nullptr, nullptr,
                                     nullptr, pf, CDIM, HIDDIM);
    mma_gemm<1><<<gP, 256, GSMEM>>>(pf, pw2t, bf2, nullptr, nullptr, px1,
                                    out, nullptr, HIDDIM, CDIM);

    // ---- join ----
    cudaStreamWaitEvent(0, evJ, 0);
}